// round 1
// baseline (speedup 1.0000x reference)
#include <cuda_runtime.h>
#include <math.h>

// Problem constants
constexpr int SEQ  = 2048;
constexpr int DIM  = 2048;
constexpr int NHEADS = 16;
constexpr int NKV    = 4;
constexpr int HDIM   = 128;
constexpr int FFD    = 8192;
constexpr float EPSV = 1e-6f;

// ---------------------------------------------------------------------------
// Scratch buffers (device globals — no allocation allowed)
// ---------------------------------------------------------------------------
__device__ float g_h1[(long)SEQ * DIM];
__device__ float g_q [(long)SEQ * NHEADS * HDIM];
__device__ float g_k [(long)SEQ * NKV * HDIM];
__device__ float g_v [(long)SEQ * NKV * HDIM];
__device__ float g_sc[(long)NHEADS * SEQ * SEQ];   // scores -> probs (256 MB)
__device__ float g_at[(long)SEQ * NHEADS * HDIM];  // attn output [S, H*HD]
__device__ float g_x2[(long)SEQ * DIM];
__device__ float g_h2[(long)SEQ * DIM];
__device__ float g_g [(long)SEQ * FFD];            // gate proj
__device__ float g_m [(long)SEQ * FFD];            // silu(g)*u

// ---------------------------------------------------------------------------
// RMSNorm: one block per row
// ---------------------------------------------------------------------------
__global__ __launch_bounds__(256)
void rmsnorm_kernel(const float* __restrict__ x, const float* __restrict__ w,
                    float* __restrict__ o)
{
    const int row = blockIdx.x;
    const float* xr = x + (long)row * DIM;
    float s = 0.f;
    for (int j = threadIdx.x; j < DIM; j += 256) {
        float v = xr[j];
        s += v * v;
    }
    __shared__ float red[256];
    red[threadIdx.x] = s;
    __syncthreads();
    for (int st = 128; st > 0; st >>= 1) {
        if (threadIdx.x < st) red[threadIdx.x] += red[threadIdx.x + st];
        __syncthreads();
    }
    const float inv = rsqrtf(red[0] * (1.0f / DIM) + EPSV);
    float* orow = o + (long)row * DIM;
    for (int j = threadIdx.x; j < DIM; j += 256)
        orow[j] = xr[j] * inv * w[j];
}

// ---------------------------------------------------------------------------
// RoPE in-place on q [S, H*HD] and k [S, KVH*HD]. 64 threads = 64 dim pairs.
// blockIdx.x = seq pos, blockIdx.y = head index (0..NHEADS-1 -> q, rest -> k)
// ---------------------------------------------------------------------------
__global__ void rope_kernel(float* __restrict__ q, float* __restrict__ k)
{
    const int s = blockIdx.x;
    const int h = blockIdx.y;
    const int d = threadIdx.x;  // 0..63
    float* base = (h < NHEADS)
        ? (q + (long)s * (NHEADS * HDIM) + h * HDIM)
        : (k + (long)s * (NKV * HDIM) + (h - NHEADS) * HDIM);
    const double ang = (double)s * pow(10000.0, -(double)d / 64.0);
    const float c  = (float)cos(ang);
    const float sn = (float)sin(ang);
    const float x0 = base[d];
    const float x1 = base[d + 64];
    base[d]      = x0 * c - x1 * sn;   // rotate_half: first half uses -x[d+64]
    base[d + 64] = x1 * c + x0 * sn;   // second half uses +x[d]
}

// ---------------------------------------------------------------------------
// Causal softmax over scores row. Writes probs (zeros above the diagonal).
// blockIdx.x = query row, blockIdx.y = head
// ---------------------------------------------------------------------------
__global__ __launch_bounds__(256)
void softmax_kernel(float* __restrict__ scores)
{
    const int srow = blockIdx.x;
    const int h    = blockIdx.y;
    float* row = scores + ((long)h * SEQ + srow) * SEQ;
    const int n = srow + 1;

    __shared__ float buf[SEQ];
    __shared__ float red[256];
    const int tid = threadIdx.x;

    float mx = -1e30f;
    for (int j = tid; j < n; j += 256) {
        float v = row[j];
        buf[j] = v;
        mx = fmaxf(mx, v);
    }
    red[tid] = mx;
    __syncthreads();
    for (int st = 128; st > 0; st >>= 1) {
        if (tid < st) red[tid] = fmaxf(red[tid], red[tid + st]);
        __syncthreads();
    }
    mx = red[0];
    __syncthreads();

    float sum = 0.f;
    for (int j = tid; j < n; j += 256) {
        float e = expf(buf[j] - mx);
        buf[j] = e;
        sum += e;
    }
    red[tid] = sum;
    __syncthreads();
    for (int st = 128; st > 0; st >>= 1) {
        if (tid < st) red[tid] += red[tid + st];
        __syncthreads();
    }
    const float inv = 1.0f / red[0];
    for (int j = tid; j < SEQ; j += 256)
        row[j] = (j < n) ? buf[j] * inv : 0.0f;
}

// ---------------------------------------------------------------------------
// Generic tiled fp32 GEMM: C[M,N] = op(A[M,K] x B), batched via blockIdx.z.
//   BT=false: B row-major [K,N]   BT=true: B row-major [N,K] (i.e. A x B^T)
// Epilogue modes:
//   0 NONE   : C = acc
//   1 RESID  : C = acc + Aux      (Aux addressed like C)
//   2 SCORES : if (col<=row) C = acc*scale  (causal; skips masked writes)
//   3 SILU   : C = silu(Aux) * acc
// Batch: A += z*sA; B += (z/bGroup)*sB; C += z*sC  (GQA via bGroup)
// Block: 128x128, BK=8, 256 threads, 8x8 per thread.
// Requires M%128==0, N%128==0, K%8==0 (true for all calls here).
// ---------------------------------------------------------------------------
template<int MODE, bool BT>
__global__ __launch_bounds__(256)
void gemm_kernel(const float* __restrict__ A, const float* __restrict__ B,
                 float* __restrict__ C, const float* __restrict__ Aux,
                 int M, int N, int K, int lda, int ldb, int ldc,
                 long sA, long sB, long sC, int bGroup, float scale)
{
    const int bz = blockIdx.z;
    A += (long)bz * sA;
    B += (long)(bz / bGroup) * sB;
    C += (long)bz * sC;

    const int row0 = blockIdx.y * 128;
    const int col0 = blockIdx.x * 128;
    if (MODE == 2 && col0 > row0 + 127) return;  // fully-masked tile

    __shared__ float As[8][128];
    __shared__ float Bs[8][128];

    const int tid  = threadIdx.x;
    const int aRow = tid >> 1;          // 0..127
    const int aCol = (tid & 1) << 2;    // 0 or 4
    const int bRow = tid >> 5;          // 0..7   (NN B load)
    const int bCol = (tid & 31) << 2;   // 0..124
    const int ty   = tid >> 4;          // 0..15
    const int tx   = tid & 15;          // 0..15

    float acc[8][8];
#pragma unroll
    for (int i = 0; i < 8; i++)
#pragma unroll
        for (int j = 0; j < 8; j++) acc[i][j] = 0.f;

    for (int k0 = 0; k0 < K; k0 += 8) {
        float4 av = *(const float4*)(A + (long)(row0 + aRow) * lda + k0 + aCol);
        As[aCol + 0][aRow] = av.x;
        As[aCol + 1][aRow] = av.y;
        As[aCol + 2][aRow] = av.z;
        As[aCol + 3][aRow] = av.w;
        if (BT) {
            float4 bv = *(const float4*)(B + (long)(col0 + aRow) * ldb + k0 + aCol);
            Bs[aCol + 0][aRow] = bv.x;
            Bs[aCol + 1][aRow] = bv.y;
            Bs[aCol + 2][aRow] = bv.z;
            Bs[aCol + 3][aRow] = bv.w;
        } else {
            float4 bv = *(const float4*)(B + (long)(k0 + bRow) * ldb + col0 + bCol);
            *(float4*)(&Bs[bRow][bCol]) = bv;
        }
        __syncthreads();

#pragma unroll
        for (int kk = 0; kk < 8; kk++) {
            float ra[8], rb[8];
#pragma unroll
            for (int i = 0; i < 8; i++) ra[i] = As[kk][ty * 8 + i];
#pragma unroll
            for (int j = 0; j < 8; j++) rb[j] = Bs[kk][tx * 8 + j];
#pragma unroll
            for (int i = 0; i < 8; i++)
#pragma unroll
                for (int j = 0; j < 8; j++)
                    acc[i][j] = fmaf(ra[i], rb[j], acc[i][j]);
        }
        __syncthreads();
    }

#pragma unroll
    for (int i = 0; i < 8; i++) {
        const int r = row0 + ty * 8 + i;
#pragma unroll
        for (int j = 0; j < 8; j++) {
            const int c = col0 + tx * 8 + j;
            const long idx = (long)r * ldc + c;
            if (MODE == 0) {
                C[idx] = acc[i][j];
            } else if (MODE == 1) {
                C[idx] = acc[i][j] + Aux[idx];
            } else if (MODE == 2) {
                if (c <= r) C[idx] = acc[i][j] * scale;
            } else {  // MODE == 3
                float gv = Aux[idx];
                C[idx] = (gv / (1.f + expf(-gv))) * acc[i][j];
            }
        }
    }
}

// ---------------------------------------------------------------------------
// kernel_launch
// Inputs: 0 hidden_states, 1 attention_mask (ignored: exactly causal),
// 2 ln1_w, 3 Wq, 4 Wk, 5 Wv, 6 Wo, 7 ln2_w, 8 Wg, 9 Wu, 10 Wd
// ---------------------------------------------------------------------------
extern "C" void kernel_launch(void* const* d_in, const int* in_sizes, int n_in,
                              void* d_out, int out_size)
{
    (void)in_sizes; (void)n_in; (void)out_size;
    const float* x   = (const float*)d_in[0];
    const float* ln1 = (const float*)d_in[2];
    const float* Wq  = (const float*)d_in[3];
    const float* Wk  = (const float*)d_in[4];
    const float* Wv  = (const float*)d_in[5];
    const float* Wo  = (const float*)d_in[6];
    const float* ln2 = (const float*)d_in[7];
    const float* Wg  = (const float*)d_in[8];
    const float* Wu  = (const float*)d_in[9];
    const float* Wd  = (const float*)d_in[10];
    float* out = (float*)d_out;

    float *h1, *q, *k, *v, *sc, *at, *x2, *h2, *gg, *mm;
    cudaGetSymbolAddress((void**)&h1, g_h1);
    cudaGetSymbolAddress((void**)&q,  g_q);
    cudaGetSymbolAddress((void**)&k,  g_k);
    cudaGetSymbolAddress((void**)&v,  g_v);
    cudaGetSymbolAddress((void**)&sc, g_sc);
    cudaGetSymbolAddress((void**)&at, g_at);
    cudaGetSymbolAddress((void**)&x2, g_x2);
    cudaGetSymbolAddress((void**)&h2, g_h2);
    cudaGetSymbolAddress((void**)&gg, g_g);
    cudaGetSymbolAddress((void**)&mm, g_m);

    const float iscale = 0.08838834764831843f;  // 1/sqrt(128)

    // 1) h1 = rmsnorm(x)
    rmsnorm_kernel<<<SEQ, 256>>>(x, ln1, h1);

    // 2) q,k,v projections
    gemm_kernel<0, false><<<dim3(DIM / 128, SEQ / 128, 1), 256>>>(
        h1, Wq, q, nullptr, SEQ, NHEADS * HDIM, DIM, DIM, NHEADS * HDIM,
        NHEADS * HDIM, 0, 0, 0, 1, 1.f);
    gemm_kernel<0, false><<<dim3((NKV * HDIM) / 128, SEQ / 128, 1), 256>>>(
        h1, Wk, k, nullptr, SEQ, NKV * HDIM, DIM, DIM, NKV * HDIM,
        NKV * HDIM, 0, 0, 0, 1, 1.f);
    gemm_kernel<0, false><<<dim3((NKV * HDIM) / 128, SEQ / 128, 1), 256>>>(
        h1, Wv, v, nullptr, SEQ, NKV * HDIM, DIM, DIM, NKV * HDIM,
        NKV * HDIM, 0, 0, 0, 1, 1.f);

    // 3) RoPE on q and k (20 = 16 q-heads + 4 kv-heads)
    rope_kernel<<<dim3(SEQ, NHEADS + NKV), 64>>>(q, k);

    // 4) scores[h] = causal( (q_h @ k_{h/4}^T) / sqrt(HD) )
    gemm_kernel<2, true><<<dim3(SEQ / 128, SEQ / 128, NHEADS), 256>>>(
        q, k, sc, nullptr, SEQ, SEQ, HDIM,
        NHEADS * HDIM, NKV * HDIM, SEQ,
        (long)HDIM, (long)HDIM, (long)SEQ * SEQ, NKV, iscale);

    // 5) softmax (writes zeros above diagonal)
    softmax_kernel<<<dim3(SEQ, NHEADS), 256>>>(sc);

    // 6) attn[h] = probs_h @ v_{h/4}, written to [S, H*HD]
    gemm_kernel<0, false><<<dim3(HDIM / 128, SEQ / 128, NHEADS), 256>>>(
        sc, v, at, nullptr, SEQ, HDIM, SEQ,
        SEQ, NKV * HDIM, NHEADS * HDIM,
        (long)SEQ * SEQ, (long)HDIM, (long)HDIM, NKV, 1.f);

    // 7) x2 = attn @ Wo + x
    gemm_kernel<1, false><<<dim3(DIM / 128, SEQ / 128, 1), 256>>>(
        at, Wo, x2, x, SEQ, DIM, NHEADS * HDIM,
        NHEADS * HDIM, DIM, DIM, 0, 0, 0, 1, 1.f);

    // 8) h2 = rmsnorm(x2)
    rmsnorm_kernel<<<SEQ, 256>>>(x2, ln2, h2);

    // 9) g = h2 @ Wg
    gemm_kernel<0, false><<<dim3(FFD / 128, SEQ / 128, 1), 256>>>(
        h2, Wg, gg, nullptr, SEQ, FFD, DIM, DIM, FFD, FFD, 0, 0, 0, 1, 1.f);

    // 10) m = silu(g) * (h2 @ Wu)
    gemm_kernel<3, false><<<dim3(FFD / 128, SEQ / 128, 1), 256>>>(
        h2, Wu, mm, gg, SEQ, FFD, DIM, DIM, FFD, FFD, 0, 0, 0, 1, 1.f);

    // 11) out = m @ Wd + x2
    gemm_kernel<1, false><<<dim3(DIM / 128, SEQ / 128, 1), 256>>>(
        mm, Wd, out, x2, SEQ, DIM, FFD, FFD, DIM, DIM, 0, 0, 0, 1, 1.f);
}